// round 8
// baseline (speedup 1.0000x reference)
#include <cuda_runtime.h>
#include <math.h>

// Problem constants
#define NCAM   6
#define NH     8
#define EMBD   256
#define HS     32
#define L      100
#define NKEY   600
#define TQ     8
#define NQT    13      // 13*8 = 104 >= 100

#define GTHR   256
#define ATHR   512

// GEMM: vbar(200x256) = featc(200x1536) @ Wbar(1536x256)
#define KSPLIT 32
#define KSL    48
#define TILE_N 128
#define TILE_M 64

__device__ float g_wbar[1536 * 256];
__device__ float g_part[KSPLIT * 200 * 256];
__device__ float g_vbar[200 * 256];

typedef unsigned long long ull;

__device__ __forceinline__ ull pk2(float lo, float hi) {
    ull r;
    asm("mov.b64 %0, {%1, %2};" : "=l"(r) : "f"(lo), "f"(hi));
    return r;
}
__device__ __forceinline__ void upk2(float& lo, float& hi, ull v) {
    asm("mov.b64 {%0, %1}, %2;" : "=f"(lo), "=f"(hi) : "l"(v));
}
__device__ __forceinline__ void fma2(ull& d, ull a, ull b) {
    asm("fma.rn.f32x2 %0, %1, %2, %0;" : "+l"(d) : "l"(a), "l"(b));
}

// ===========================================================================
// K0: fold W_v -> Wbar (mean over 4 ref column-blocks). 384 blocks x 256 thr.
// ===========================================================================
__global__ void __launch_bounds__(256, 4)
wbar_kernel(const float* __restrict__ Wv) {
    int idx = blockIdx.x * 256 + threadIdx.x;     // < 98304 float4 slots
    int i = idx >> 6;                              // W row 0..1535
    int e = (idx & 63) * 4;                        // col 0..252
    const float* wp = Wv + (size_t)i * 1024 + e;
    float4 x0 = *(const float4*)(wp);
    float4 x1 = *(const float4*)(wp + 256);
    float4 x2 = *(const float4*)(wp + 512);
    float4 x3 = *(const float4*)(wp + 768);
    float4 o;
    o.x = 0.25f * (x0.x + x1.x + x2.x + x3.x);
    o.y = 0.25f * (x0.y + x1.y + x2.y + x3.y);
    o.z = 0.25f * (x0.z + x1.z + x2.z + x3.z);
    o.w = 0.25f * (x0.w + x1.w + x2.w + x3.w);
    *(float4*)&g_wbar[i * 256 + e] = o;
}

// ===========================================================================
// K1: split-K GEMM, double-buffered smem, 2 CTAs/SM. 256 blocks x 256 thr.
// ===========================================================================
__global__ void __launch_bounds__(GTHR, 2)
gemm_kernel(const float* __restrict__ sff) {
    __shared__ float As[2][64 * 20];
    __shared__ float Bs[2][16 * 128];

    const int tid = threadIdx.x;
    const int bid = blockIdx.x;

    const int cb = bid & 1;
    const int rb = (bid >> 1) & 3;
    const int kz = bid >> 3;
    const int colBase = cb * TILE_N;
    const int rowBase = rb * TILE_M;
    const int k0 = kz * KSL;

    const int tx = tid & 15;
    const int ty = tid >> 4;

    // per-thread load slots
    const int rr = tid >> 2, k4 = tid & 3;          // A slot
    const int r  = rowBase + rr;
    const int bA = (r >= 100) ? 1 : 0;
    const int lA = r - 100 * bA;

    float4 aReg;
    float4 bReg[2];
    int    bKK[2], bC[2];
    #pragma unroll
    for (int t = 0; t < 2; ++t) {
        int s = tid + t * 256;
        bKK[t] = s >> 5;
        bC[t]  = (s & 31) * 4;
    }

    auto load_regs = [&](int kt) {
        {
            int i = k0 + kt + k4 * 4;
            int cam = i >> 8, ep = i & 255;
            aReg = (r < 200) ? *(const float4*)&sff[(bA * NCAM + cam) * 25600 + lA * 256 + ep]
                             : make_float4(0.f, 0.f, 0.f, 0.f);
        }
        #pragma unroll
        for (int t = 0; t < 2; ++t)
            bReg[t] = *(const float4*)&g_wbar[(k0 + kt + bKK[t]) * 256 + colBase + bC[t]];
    };
    auto store_smem = [&](int buf) {
        *(float4*)&As[buf][rr * 20 + k4 * 4] = aReg;
        #pragma unroll
        for (int t = 0; t < 2; ++t)
            *(float4*)&Bs[buf][bKK[t] * 128 + bC[t]] = bReg[t];
    };

    ull acc[4][4];
    #pragma unroll
    for (int i = 0; i < 4; ++i)
        #pragma unroll
        for (int j = 0; j < 4; ++j) acc[i][j] = 0ull;

    load_regs(0);
    store_smem(0);
    load_regs(16);                 // tile 1 LDG in flight during tile 0 compute
    __syncthreads();

    #pragma unroll
    for (int t = 0; t < 3; ++t) {  // KSL/16 == 3
        const int buf = t & 1;
        #pragma unroll
        for (int kk = 0; kk < 16; ++kk) {
            ull av[4];
            #pragma unroll
            for (int i = 0; i < 4; ++i) {
                float a = As[buf][(ty * 4 + i) * 20 + kk];
                av[i] = pk2(a, a);
            }
            const ull* bp = (const ull*)&Bs[buf][kk * 128 + tx * 8];
            ull b0 = bp[0], b1 = bp[1], b2 = bp[2], b3 = bp[3];
            #pragma unroll
            for (int i = 0; i < 4; ++i) {
                fma2(acc[i][0], av[i], b0);
                fma2(acc[i][1], av[i], b1);
                fma2(acc[i][2], av[i], b2);
                fma2(acc[i][3], av[i], b3);
            }
        }
        if (t + 1 < 3) store_smem(buf ^ 1);
        if (t + 2 < 3) load_regs((t + 2) * 16);
        __syncthreads();
    }

    #pragma unroll
    for (int i = 0; i < 4; ++i) {
        int rOut = rowBase + ty * 4 + i;
        if (rOut < 200) {
            float* dst = &g_part[kz * 51200 + rOut * 256 + colBase + tx * 8];
            #pragma unroll
            for (int j = 0; j < 4; ++j) {
                float2 f;
                upk2(f.x, f.y, acc[i][j]);
                *(float2*)&dst[2 * j] = f;
            }
        }
    }
}

// ===========================================================================
// K2: reduce split-K partials + folded bias -> g_vbar.  50 blocks x 256 thr.
// ===========================================================================
__global__ void __launch_bounds__(256, 4)
vred_kernel(const float* __restrict__ bv) {
    int idx = blockIdx.x * 256 + threadIdx.x;     // < 12800 float4 slots
    int r = idx >> 6;
    int e = (idx & 63) * 4;
    float4 b0 = *(const float4*)&bv[e];
    float4 b1 = *(const float4*)&bv[e + 256];
    float4 b2 = *(const float4*)&bv[e + 512];
    float4 b3 = *(const float4*)&bv[e + 768];
    float4 a;
    a.x = 0.25f * (b0.x + b1.x + b2.x + b3.x);
    a.y = 0.25f * (b0.y + b1.y + b2.y + b3.y);
    a.z = 0.25f * (b0.z + b1.z + b2.z + b3.z);
    a.w = 0.25f * (b0.w + b1.w + b2.w + b3.w);
    #pragma unroll
    for (int kz = 0; kz < KSPLIT; ++kz) {
        float4 p = *(const float4*)&g_part[kz * 51200 + r * 256 + e];
        a.x += p.x; a.y += p.y; a.z += p.z; a.w += p.w;
    }
    *(float4*)&g_vbar[r * 256 + e] = a;
}

// ===========================================================================
// K3: attention. 208 blocks x 512 thr, 2 CTAs/SM (109.8KB smem). (validated)
// ===========================================================================
// smem floats: Qt[32][8] | Kt[600][32] swizzled | Vs[100][32] | S[8][600]
#define OFF_QT  0
#define OFF_KT  256
#define OFF_VS  (OFF_KT + NKEY * 32)
#define OFF_S   (OFF_VS + L * HS)
#define SMEM_FLOATS (OFF_S + TQ * NKEY)
#define SMEM_BYTES  (SMEM_FLOATS * 4)

__global__ void __launch_bounds__(ATHR, 2)
attn_kernel(const float* __restrict__ sff, const float* __restrict__ bq,
            float* __restrict__ out) {
    extern __shared__ float sm[];
    float* Qt = sm + OFF_QT;   // [d][8], pre-scaled
    float* Kt = sm + OFF_KT;   // [k][32], slot = g ^ (k&7)
    float* Vs = sm + OFF_VS;   // [lp][32]
    float* S  = sm + OFF_S;    // [q][600]; after softmax, [q][0..99] = weights

    const int tid  = threadIdx.x;
    const int w    = tid >> 5;
    const int lane = tid & 31;
    const int bid  = blockIdx.x;
    const int qb = bid % NQT;
    const int h  = (bid / NQT) % NH;
    const int b  = bid / (NQT * NH);
    const int q0 = qb * TQ;

    // ---- Keys: batched coalesced LDG.128 -> swizzled STS.128 ---------------
    {
        float4 kreg[9];
        int    kaddr[9];
        #pragma unroll
        for (int i = 0; i < 9; ++i) {
            int idx = tid + i * 512;
            int k = idx >> 3, g = idx & 7;
            int cam = k / 100, lp = k - cam * 100;
            kreg[i] = *(const float4*)&sff[(b * NCAM + cam) * 25600 + lp * 256 + h * 32 + g * 4];
            kaddr[i] = k * 32 + (g ^ (k & 7)) * 4;
        }
        float4 kx; int kxaddr = -1;
        if (tid < 192) {
            int idx = tid + 4608;
            int k = idx >> 3, g = idx & 7;
            int cam = k / 100, lp = k - cam * 100;
            kx = *(const float4*)&sff[(b * NCAM + cam) * 25600 + lp * 256 + h * 32 + g * 4];
            kxaddr = k * 32 + (g ^ (k & 7)) * 4;
        }
        #pragma unroll
        for (int i = 0; i < 9; ++i)
            *(float4*)&Kt[kaddr[i]] = kreg[i];
        if (kxaddr >= 0)
            *(float4*)&Kt[kxaddr] = kx;
    }
    // ---- Values: simple float4 loads from g_vbar ---------------------------
    #pragma unroll
    for (int i = 0; i < 2; ++i) {
        int idx = tid + i * 512;
        if (idx < L * 8) {
            int lp = idx >> 3, dg = idx & 7;
            *(float4*)&Vs[lp * 32 + dg * 4] =
                *(const float4*)&g_vbar[(b * 100 + lp) * 256 + h * 32 + dg * 4];
        }
    }
    // ---- Queries: Qt[d][8], pre-scaled, clamped ragged tail ----------------
    if (tid < 256) {
        int d = tid >> 3, qi = tid & 7;
        int qg = q0 + qi; if (qg > 99) qg = 99;
        Qt[tid] = bq[(b * L + qg) * 256 + h * 32 + d] * 0.17677669529663687f;
    }
    __syncthreads();

    // ---- scores + exp: thread owns keys k0=tid, k1=tid+512 -----------------
    {
        const int k0i = tid;
        const int k1i = tid + 512;
        const bool has1 = (k1i < NKEY);
        const int sw0 = k0i & 7;          // (k1i & 7) == sw0
        ull acc0[4], acc1[4];
        #pragma unroll
        for (int p = 0; p < 4; ++p) { acc0[p] = 0ull; acc1[p] = 0ull; }

        #pragma unroll
        for (int g = 0; g < 8; ++g) {
            float4 kv0 = *(const float4*)&Kt[k0i * 32 + (g ^ sw0) * 4];
            float4 kv1 = has1 ? *(const float4*)&Kt[k1i * 32 + (g ^ sw0) * 4]
                              : make_float4(0.f, 0.f, 0.f, 0.f);
            const float kj0[4] = {kv0.x, kv0.y, kv0.z, kv0.w};
            const float kj1[4] = {kv1.x, kv1.y, kv1.z, kv1.w};
            #pragma unroll
            for (int j = 0; j < 4; ++j) {
                int d = g * 4 + j;
                ull kd0 = pk2(kj0[j], kj0[j]);
                ull kd1 = pk2(kj1[j], kj1[j]);
                ulonglong2 qa = *(const ulonglong2*)&Qt[d * 8];
                ulonglong2 qc = *(const ulonglong2*)&Qt[d * 8 + 4];
                fma2(acc0[0], qa.x, kd0);
                fma2(acc0[1], qa.y, kd0);
                fma2(acc0[2], qc.x, kd0);
                fma2(acc0[3], qc.y, kd0);
                fma2(acc1[0], qa.x, kd1);
                fma2(acc1[1], qa.y, kd1);
                fma2(acc1[2], qc.x, kd1);
                fma2(acc1[3], qc.y, kd1);
            }
        }
        #pragma unroll
        for (int p = 0; p < 4; ++p) {
            float lo, hi;
            upk2(lo, hi, acc0[p]);
            S[(2 * p) * NKEY + k0i]     = __expf(lo);
            S[(2 * p + 1) * NKEY + k0i] = __expf(hi);
            if (has1) {
                upk2(lo, hi, acc1[p]);
                S[(2 * p) * NKEY + k1i]     = __expf(lo);
                S[(2 * p + 1) * NKEY + k1i] = __expf(hi);
            }
        }
    }
    __syncthreads();

    // ---- softmax: warp w < 8 handles query q = w; normalize in place -------
    if (w < TQ) {
        const int q = w;
        float z = 0.f;
        #pragma unroll
        for (int i = lane; i < 150; i += 32) {
            float4 v = ((const float4*)&S[q * NKEY])[i];
            z += (v.x + v.y) + (v.z + v.w);
        }
        #pragma unroll
        for (int off = 16; off; off >>= 1)
            z += __shfl_xor_sync(0xffffffffu, z, off);
        float invZ = __frcp_rn(z);
        #pragma unroll
        for (int i = lane; i < L; i += 32) {
            float s6 = S[q * NKEY + i]       + S[q * NKEY + 100 + i]
                     + S[q * NKEY + 200 + i] + S[q * NKEY + 300 + i]
                     + S[q * NKEY + 400 + i] + S[q * NKEY + 500 + i];
            S[q * NKEY + i] = s6 * invZ;
        }
    }
    __syncthreads();

    // ---- output: out[q,d] = sum_lp S[q,lp] * Vs[lp,d] ----------------------
    if (w < TQ) {
        const int q = w, d = lane;
        int qg = q0 + q;
        float acc = 0.f;
        #pragma unroll 4
        for (int lp = 0; lp < L; ++lp)
            acc = fmaf(S[q * NKEY + lp], Vs[lp * 32 + d], acc);
        if (qg < 100)
            out[(b * L + qg) * 256 + h * 32 + d] = acc;
    }
}

// ---------------------------------------------------------------------------
extern "C" void kernel_launch(void* const* d_in, const int* in_sizes, int n_in,
                              void* d_out, int out_size) {
    const float* sff = (const float*)d_in[0];
    const float* bq  = (const float*)d_in[1];
    const float* Wv  = (const float*)d_in[2];
    const float* bv  = (const float*)d_in[3];
    float* out = (float*)d_out;

    cudaFuncSetAttribute(attn_kernel, cudaFuncAttributeMaxDynamicSharedMemorySize,
                         SMEM_BYTES);
    wbar_kernel<<<384, 256>>>(Wv);
    gemm_kernel<<<256, GTHR>>>(sff);
    vred_kernel<<<50, 256>>>(bv);
    attn_kernel<<<NQT * NH * 2, ATHR, SMEM_BYTES>>>(sff, bq, out);
}

// round 9
// speedup vs baseline: 1.4003x; 1.4003x over previous
#include <cuda_runtime.h>
#include <math.h>

// Problem constants
#define NCAM   6
#define NH     8
#define EMBD   256
#define HS     32
#define L      100
#define NKEY   600
#define TQ     8
#define NQT    13      // 13*8 = 104 >= 100

#define ATHR   512

// GEMM: vbar(200x256) = featc(200x1536) @ Wbar(1536x256)
// 64x64 tiles, KSPLIT=8 (KSL=192): grid = 4 cb * 4 rb * 8 kz = 128 blocks
#define KSPLIT 8
#define KSL    192

__device__ float g_part[KSPLIT * 200 * 256];

typedef unsigned long long ull;

__device__ __forceinline__ ull pk2(float lo, float hi) {
    ull r;
    asm("mov.b64 %0, {%1, %2};" : "=l"(r) : "f"(lo), "f"(hi));
    return r;
}
__device__ __forceinline__ void upk2(float& lo, float& hi, ull v) {
    asm("mov.b64 {%0, %1}, %2;" : "=f"(lo), "=f"(hi) : "l"(v));
}
__device__ __forceinline__ void fma2(ull& d, ull a, ull b) {
    asm("fma.rn.f32x2 %0, %1, %2, %0;" : "+l"(d) : "l"(a), "l"(b));
}

// ===========================================================================
// K1: split-K GEMM, inline W_v fold (each W_v element folded exactly once
// chip-wide), double-buffered smem, loads issued before compute.
// 128 blocks x 256 thr.
// ===========================================================================
__global__ void __launch_bounds__(256, 2)
gemm_kernel(const float* __restrict__ sff, const float* __restrict__ Wv) {
    __shared__ float As[2][64 * 20];   // [rr][kk], stride 20
    __shared__ float Bs[2][16 * 64];   // [kk][c]

    const int tid = threadIdx.x;
    const int bid = blockIdx.x;

    const int cb = bid & 3;
    const int rb = (bid >> 2) & 3;
    const int kz = bid >> 4;
    const int colBase = cb * 64;
    const int rowBase = rb * 64;
    const int k0 = kz * KSL;

    const int tx = tid & 15;           // 4 output cols each
    const int ty = tid >> 4;           // 4 output rows each

    // A load slot: one float4 per thread per tile
    const int rr = tid >> 2, k4 = tid & 3;
    const int r  = rowBase + rr;
    const int bA = (r >= 100) ? 1 : 0;
    const int lA = r - 100 * bA;
    // B load slot: one folded float4 per thread per tile
    const int kkB = tid >> 4, cB = (tid & 15) * 4;

    float4 aReg, bReg;
    auto load_regs = [&](int kt) {
        {
            int i = k0 + kt + k4 * 4;
            int cam = i >> 8, ep = i & 255;
            aReg = (r < 200) ? *(const float4*)&sff[(bA * NCAM + cam) * 25600 + lA * 256 + ep]
                             : make_float4(0.f, 0.f, 0.f, 0.f);
        }
        {
            const float* wp = Wv + (size_t)(k0 + kt + kkB) * 1024 + colBase + cB;
            float4 x0 = *(const float4*)(wp);
            float4 x1 = *(const float4*)(wp + 256);
            float4 x2 = *(const float4*)(wp + 512);
            float4 x3 = *(const float4*)(wp + 768);
            bReg.x = 0.25f * (x0.x + x1.x + x2.x + x3.x);
            bReg.y = 0.25f * (x0.y + x1.y + x2.y + x3.y);
            bReg.z = 0.25f * (x0.z + x1.z + x2.z + x3.z);
            bReg.w = 0.25f * (x0.w + x1.w + x2.w + x3.w);
        }
    };
    auto store_smem = [&](int buf) {
        *(float4*)&As[buf][rr * 20 + k4 * 4] = aReg;
        *(float4*)&Bs[buf][kkB * 64 + cB]   = bReg;
    };

    ull acc[4][2];
    #pragma unroll
    for (int i = 0; i < 4; ++i) { acc[i][0] = 0ull; acc[i][1] = 0ull; }

    load_regs(0);
    store_smem(0);
    load_regs(16);
    __syncthreads();

    #pragma unroll
    for (int t = 0; t < 12; ++t) {     // KSL/16 == 12
        const int buf = t & 1;
        // regs currently hold tile t+1; buf^1 (tile t-1) is free after the sync
        if (t + 1 < 12) store_smem(buf ^ 1);
        if (t + 2 < 12) load_regs((t + 2) * 16);   // LDGs in flight during compute

        #pragma unroll
        for (int kk = 0; kk < 16; ++kk) {
            ull av[4];
            #pragma unroll
            for (int i = 0; i < 4; ++i) {
                float a = As[buf][(ty * 4 + i) * 20 + kk];
                av[i] = pk2(a, a);
            }
            const ull* bp = (const ull*)&Bs[buf][kk * 64 + tx * 4];
            ull b0 = bp[0], b1 = bp[1];
            #pragma unroll
            for (int i = 0; i < 4; ++i) {
                fma2(acc[i][0], av[i], b0);
                fma2(acc[i][1], av[i], b1);
            }
        }
        __syncthreads();
    }

    #pragma unroll
    for (int i = 0; i < 4; ++i) {
        int rOut = rowBase + ty * 4 + i;
        if (rOut < 200) {
            float4 f;
            upk2(f.x, f.y, acc[i][0]);
            upk2(f.z, f.w, acc[i][1]);
            *(float4*)&g_part[kz * 51200 + rOut * 256 + colBase + tx * 4] = f;
        }
    }
}

// ===========================================================================
// K2: attention. 208 blocks x 512 thr, 2 CTAs/SM (109.8KB smem).
// Vs = sum of 8 split-K partials + folded bias (inline, overlapped).
// ===========================================================================
// smem floats: Qt[32][8] | Kt[600][32] swizzled | Vs[100][32] | S[8][600]
#define OFF_QT  0
#define OFF_KT  256
#define OFF_VS  (OFF_KT + NKEY * 32)
#define OFF_S   (OFF_VS + L * HS)
#define SMEM_FLOATS (OFF_S + TQ * NKEY)
#define SMEM_BYTES  (SMEM_FLOATS * 4)

__global__ void __launch_bounds__(ATHR, 2)
attn_kernel(const float* __restrict__ sff, const float* __restrict__ bq,
            const float* __restrict__ bv, float* __restrict__ out) {
    extern __shared__ float sm[];
    float* Qt = sm + OFF_QT;   // [d][8], pre-scaled
    float* Kt = sm + OFF_KT;   // [k][32], slot = g ^ (k&7)
    float* Vs = sm + OFF_VS;   // [lp][32]
    float* S  = sm + OFF_S;    // [q][600]; after softmax, [q][0..99] = weights

    const int tid  = threadIdx.x;
    const int w    = tid >> 5;
    const int lane = tid & 31;
    const int bid  = blockIdx.x;
    const int qb = bid % NQT;
    const int h  = (bid / NQT) % NH;
    const int b  = bid / (NQT * NH);
    const int q0 = qb * TQ;

    // ---- Keys: batched coalesced LDG.128 -> swizzled STS.128 ---------------
    {
        float4 kreg[9];
        int    kaddr[9];
        #pragma unroll
        for (int i = 0; i < 9; ++i) {
            int idx = tid + i * 512;
            int k = idx >> 3, g = idx & 7;
            int cam = k / 100, lp = k - cam * 100;
            kreg[i] = *(const float4*)&sff[(b * NCAM + cam) * 25600 + lp * 256 + h * 32 + g * 4];
            kaddr[i] = k * 32 + (g ^ (k & 7)) * 4;
        }
        float4 kx; int kxaddr = -1;
        if (tid < 192) {
            int idx = tid + 4608;
            int k = idx >> 3, g = idx & 7;
            int cam = k / 100, lp = k - cam * 100;
            kx = *(const float4*)&sff[(b * NCAM + cam) * 25600 + lp * 256 + h * 32 + g * 4];
            kxaddr = k * 32 + (g ^ (k & 7)) * 4;
        }
        #pragma unroll
        for (int i = 0; i < 9; ++i)
            *(float4*)&Kt[kaddr[i]] = kreg[i];
        if (kxaddr >= 0)
            *(float4*)&Kt[kxaddr] = kx;
    }
    // ---- Values: reduce 8 split-K partials + folded bias -------------------
    #pragma unroll
    for (int i = 0; i < 2; ++i) {
        int idx = tid + i * 512;
        if (idx < L * 8) {
            int lp = idx >> 3, dg = idx & 7;
            int e = h * 32 + dg * 4;
            int rr = b * 100 + lp;
            float4 b0 = *(const float4*)&bv[e];
            float4 b1 = *(const float4*)&bv[e + 256];
            float4 b2 = *(const float4*)&bv[e + 512];
            float4 b3 = *(const float4*)&bv[e + 768];
            float4 a;
            a.x = 0.25f * (b0.x + b1.x + b2.x + b3.x);
            a.y = 0.25f * (b0.y + b1.y + b2.y + b3.y);
            a.z = 0.25f * (b0.z + b1.z + b2.z + b3.z);
            a.w = 0.25f * (b0.w + b1.w + b2.w + b3.w);
            #pragma unroll
            for (int kz = 0; kz < KSPLIT; ++kz) {
                float4 p = *(const float4*)&g_part[kz * 51200 + rr * 256 + e];
                a.x += p.x; a.y += p.y; a.z += p.z; a.w += p.w;
            }
            *(float4*)&Vs[lp * 32 + dg * 4] = a;
        }
    }
    // ---- Queries: Qt[d][8], pre-scaled, clamped ragged tail ----------------
    if (tid < 256) {
        int d = tid >> 3, qi = tid & 7;
        int qg = q0 + qi; if (qg > 99) qg = 99;
        Qt[tid] = bq[(b * L + qg) * 256 + h * 32 + d] * 0.17677669529663687f;
    }
    __syncthreads();

    // ---- scores + exp: thread owns keys k0=tid, k1=tid+512 -----------------
    {
        const int k0i = tid;
        const int k1i = tid + 512;
        const bool has1 = (k1i < NKEY);
        const int sw0 = k0i & 7;          // (k1i & 7) == sw0
        ull acc0[4], acc1[4];
        #pragma unroll
        for (int p = 0; p < 4; ++p) { acc0[p] = 0ull; acc1[p] = 0ull; }

        #pragma unroll
        for (int g = 0; g < 8; ++g) {
            float4 kv0 = *(const float4*)&Kt[k0i * 32 + (g ^ sw0) * 4];
            float4 kv1 = has1 ? *(const float4*)&Kt[k1i * 32 + (g ^ sw0) * 4]
                              : make_float4(0.f, 0.f, 0.f, 0.f);
            const float kj0[4] = {kv0.x, kv0.y, kv0.z, kv0.w};
            const float kj1[4] = {kv1.x, kv1.y, kv1.z, kv1.w};
            #pragma unroll
            for (int j = 0; j < 4; ++j) {
                int d = g * 4 + j;
                ull kd0 = pk2(kj0[j], kj0[j]);
                ull kd1 = pk2(kj1[j], kj1[j]);
                ulonglong2 qa = *(const ulonglong2*)&Qt[d * 8];
                ulonglong2 qc = *(const ulonglong2*)&Qt[d * 8 + 4];
                fma2(acc0[0], qa.x, kd0);
                fma2(acc0[1], qa.y, kd0);
                fma2(acc0[2], qc.x, kd0);
                fma2(acc0[3], qc.y, kd0);
                fma2(acc1[0], qa.x, kd1);
                fma2(acc1[1], qa.y, kd1);
                fma2(acc1[2], qc.x, kd1);
                fma2(acc1[3], qc.y, kd1);
            }
        }
        #pragma unroll
        for (int p = 0; p < 4; ++p) {
            float lo, hi;
            upk2(lo, hi, acc0[p]);
            S[(2 * p) * NKEY + k0i]     = __expf(lo);
            S[(2 * p + 1) * NKEY + k0i] = __expf(hi);
            if (has1) {
                upk2(lo, hi, acc1[p]);
                S[(2 * p) * NKEY + k1i]     = __expf(lo);
                S[(2 * p + 1) * NKEY + k1i] = __expf(hi);
            }
        }
    }
    __syncthreads();

    // ---- softmax: warp w < 8 handles query q = w; normalize in place -------
    if (w < TQ) {
        const int q = w;
        float z = 0.f;
        #pragma unroll
        for (int i = lane; i < 150; i += 32) {
            float4 v = ((const float4*)&S[q * NKEY])[i];
            z += (v.x + v.y) + (v.z + v.w);
        }
        #pragma unroll
        for (int off = 16; off; off >>= 1)
            z += __shfl_xor_sync(0xffffffffu, z, off);
        float invZ = __frcp_rn(z);
        #pragma unroll
        for (int i = lane; i < L; i += 32) {
            float s6 = S[q * NKEY + i]       + S[q * NKEY + 100 + i]
                     + S[q * NKEY + 200 + i] + S[q * NKEY + 300 + i]
                     + S[q * NKEY + 400 + i] + S[q * NKEY + 500 + i];
            S[q * NKEY + i] = s6 * invZ;
        }
    }
    __syncthreads();

    // ---- output: out[q,d] = sum_lp S[q,lp] * Vs[lp,d] ----------------------
    if (w < TQ) {
        const int q = w, d = lane;
        int qg = q0 + q;
        float acc = 0.f;
        #pragma unroll 4
        for (int lp = 0; lp < L; ++lp)
            acc = fmaf(S[q * NKEY + lp], Vs[lp * 32 + d], acc);
        if (qg < 100)
            out[(b * L + qg) * 256 + h * 32 + d] = acc;
    }
}

// ---------------------------------------------------------------------------
extern "C" void kernel_launch(void* const* d_in, const int* in_sizes, int n_in,
                              void* d_out, int out_size) {
    const float* sff = (const float*)d_in[0];
    const float* bq  = (const float*)d_in[1];
    const float* Wv  = (const float*)d_in[2];
    const float* bv  = (const float*)d_in[3];
    float* out = (float*)d_out;

    cudaFuncSetAttribute(attn_kernel, cudaFuncAttributeMaxDynamicSharedMemorySize,
                         SMEM_BYTES);
    gemm_kernel<<<128, 256>>>(sff, Wv);
    attn_kernel<<<NQT * NH * 2, ATHR, SMEM_BYTES>>>(sff, bq, bv, out);
}